// round 10
// baseline (speedup 1.0000x reference)
#include <cuda_runtime.h>
#include <cstdint>

// out[b,t,:] = tok_weight[x[b,t],:] + pos_weight[t,:]
// B=4, T=4096, E=512 fp32.
//
// R10: write-path experiment. Gathers as before (warp per (t, quarter), pos
// loaded once and reused across the 4 batch rows), but results are staged in
// shared memory and written out with TMA bulk stores
// (cp.async.bulk.global.shared::cta), one 2KB row per copy. If the scattered
// STG stream was losing DRAM-write efficiency, full-line bulk stores fix it.
//
// CTA = 256 threads (8 warps) handles 2 time steps x 4 batches = 8 output
// rows of 2KB staged in 16KB static smem. Warp w: t_local = w&1, quarter =
// w>>1. Thread 0 issues the 8 bulk copies after a proxy fence.

__global__ void __launch_bounds__(256) pos_embed_kernel(
    const int* __restrict__ x,            // [4*T]
    const float4* __restrict__ tok_w,     // [VOCAB, 128] float4
    const float4* __restrict__ pos_w,     // [T, 128] float4
    float* __restrict__ out,              // [4*T, 512]
    int T)                                // 4096
{
    __shared__ alignas(1024) float4 stage[8 * 128];   // 8 rows x 2KB = 16KB

    const int t0   = blockIdx.x * 2;
    const int wid  = threadIdx.x >> 5;
    const int lane = threadIdx.x & 31;
    const int t_local = wid & 1;               // which of the 2 time steps
    const int q       = wid >> 1;              // column quarter 0..3
    const int t       = t0 + t_local;
    const int col     = q * 32 + lane;         // float4 column 0..127

    // Hoisted per-warp index loads
    const int tokA = __ldg(&x[t]);
    const int tokB = __ldg(&x[t + T]);
    const int tokC = __ldg(&x[t + 2 * T]);
    const int tokD = __ldg(&x[t + 3 * T]);

    // pos quarter-slice, reused by all 4 batch rows
    const float4 p = __ldg(pos_w + (long long)t * 128 + col);

    float4 a = __ldg(tok_w + (long long)tokA * 128 + col);
    float4 b = __ldg(tok_w + (long long)tokB * 128 + col);
    float4 c = __ldg(tok_w + (long long)tokC * 128 + col);
    float4 d = __ldg(tok_w + (long long)tokD * 128 + col);

    // smem row index = b*2 + t_local; each row is 128 float4
    float4 r;
    r.x = a.x + p.x; r.y = a.y + p.y; r.z = a.z + p.z; r.w = a.w + p.w;
    stage[(0 * 2 + t_local) * 128 + col] = r;
    r.x = b.x + p.x; r.y = b.y + p.y; r.z = b.z + p.z; r.w = b.w + p.w;
    stage[(1 * 2 + t_local) * 128 + col] = r;
    r.x = c.x + p.x; r.y = c.y + p.y; r.z = c.z + p.z; r.w = c.w + p.w;
    stage[(2 * 2 + t_local) * 128 + col] = r;
    r.x = d.x + p.x; r.y = d.y + p.y; r.z = d.z + p.z; r.w = d.w + p.w;
    stage[(3 * 2 + t_local) * 128 + col] = r;

    __syncthreads();

    if (threadIdx.x == 0) {
        // Make generic-proxy smem writes visible to the async (TMA) proxy.
        asm volatile("fence.proxy.async.shared::cta;" ::: "memory");

        uint32_t sbase;
        asm("{ .reg .u64 tmp; cvta.to.shared.u64 tmp, %1; cvt.u32.u64 %0, tmp; }"
            : "=r"(sbase) : "l"(stage));

        #pragma unroll
        for (int row = 0; row < 8; row++) {
            const int bb = row >> 1;
            const int tt = t0 + (row & 1);
            float* gdst = out + ((long long)bb * T + tt) * 512;
            asm volatile(
                "cp.async.bulk.global.shared::cta.bulk_group [%0], [%1], %2;"
                :: "l"(gdst), "r"(sbase + row * 2048), "r"(2048) : "memory");
        }
        asm volatile("cp.async.bulk.commit_group;" ::: "memory");
        asm volatile("cp.async.bulk.wait_group 0;" ::: "memory");
    }
}

extern "C" void kernel_launch(void* const* d_in, const int* in_sizes, int n_in,
                              void* d_out, int out_size) {
    const int*    x     = (const int*)d_in[0];
    const float4* tok_w = (const float4*)d_in[1];
    const float4* pos_w = (const float4*)d_in[2];
    float*        out   = (float*)d_out;

    const int T = 4096;                       // fixed problem shape (B=4)
    const int threads = 256;                  // 8 warps: 2 t x 4 quarters
    int blocks = T / 2;                       // 2048 CTAs

    pos_embed_kernel<<<blocks, threads>>>(x, tok_w, pos_w, out, T);
}